// round 14
// baseline (speedup 1.0000x reference)
#include <cuda_runtime.h>
#include <cstddef>

// Row-normalize block-diagonal graph — THREE rows per warp, full front-batch.
//
// edge_weight: [K, N*N] fp32, N=1024. row[e]=e/N closed-form -> degree of
// source node r = sum of contiguous 1024-float row r. out = w * 1/deg.
//
// Cross-round model: DRAM% tracks aggregate in-flight read bytes per SM
// (warps x front-batched LDG.128): 248->75.6%, 304->77.1% (R10, best),
// 214->72.1%. Pipelining/scheduling games all lost; only batch depth x
// resident warps matters. This probes the last untested point on that axis:
// 24 LDG.128 front-batched per thread (3 adjacent rows), ~128 regs ->
// 2 blocks/SM = 16 warps -> ~384 in-flight units (+26% vs R10).

static constexpr int N_ATOM = 1024;                    // floats per row
static constexpr int F4_PER_LANE = N_ATOM / (32 * 4);  // 8
static constexpr int F4_PER_ROW = N_ATOM / 4;          // 256
static constexpr int ROWS_PER_WARP = 3;

__global__ __launch_bounds__(256) void rownorm_3row_kernel(
    const float* __restrict__ w,
    float* __restrict__ out,
    int ngroups)   // ceil(nrows / 3)
{
    int gtid = blockIdx.x * blockDim.x + threadIdx.x;
    int warp = gtid >> 5;
    int lane = threadIdx.x & 31;
    if (warp >= ngroups) return;

    const float4* __restrict__ wp =
        reinterpret_cast<const float4*>(w) + (size_t)warp * ROWS_PER_WARP * F4_PER_ROW;
    float4* __restrict__ op =
        reinterpret_cast<float4*>(out) + (size_t)warp * ROWS_PER_WARP * F4_PER_ROW;

    // Front-batch ALL 24 LDG.128 per thread (3 rows).
    float4 v0[F4_PER_LANE], v1[F4_PER_LANE], v2[F4_PER_LANE];
#pragma unroll
    for (int i = 0; i < F4_PER_LANE; i++) v0[i] = wp[lane + i * 32];
#pragma unroll
    for (int i = 0; i < F4_PER_LANE; i++) v1[i] = wp[F4_PER_ROW + lane + i * 32];
#pragma unroll
    for (int i = 0; i < F4_PER_LANE; i++) v2[i] = wp[2 * F4_PER_ROW + lane + i * 32];

    float a = 0.0f, b = 0.0f, c = 0.0f;
#pragma unroll
    for (int i = 0; i < F4_PER_LANE; i++) {
        a += (v0[i].x + v0[i].y) + (v0[i].z + v0[i].w);
        b += (v1[i].x + v1[i].y) + (v1[i].z + v1[i].w);
        c += (v2[i].x + v2[i].y) + (v2[i].z + v2[i].w);
    }

    // Three independent warp tree-reduces, interleaved.
#pragma unroll
    for (int off = 16; off > 0; off >>= 1) {
        a += __shfl_xor_sync(0xFFFFFFFFu, a, off);
        b += __shfl_xor_sync(0xFFFFFFFFu, b, off);
        c += __shfl_xor_sync(0xFFFFFFFFu, c, off);
    }

    float inv0 = (a > 0.0f) ? (1.0f / a) : 0.0f;
    float inv1 = (b > 0.0f) ? (1.0f / b) : 0.0f;
    float inv2 = (c > 0.0f) ? (1.0f / c) : 0.0f;

    // Scale in registers, store all three rows.
#pragma unroll
    for (int i = 0; i < F4_PER_LANE; i++) {
        float4 t = v0[i];
        t.x *= inv0; t.y *= inv0; t.z *= inv0; t.w *= inv0;
        op[lane + i * 32] = t;
    }
#pragma unroll
    for (int i = 0; i < F4_PER_LANE; i++) {
        float4 t = v1[i];
        t.x *= inv1; t.y *= inv1; t.z *= inv1; t.w *= inv1;
        op[F4_PER_ROW + lane + i * 32] = t;
    }
#pragma unroll
    for (int i = 0; i < F4_PER_LANE; i++) {
        float4 t = v2[i];
        t.x *= inv2; t.y *= inv2; t.z *= inv2; t.w *= inv2;
        op[2 * F4_PER_ROW + lane + i * 32] = t;
    }
}

extern "C" void kernel_launch(void* const* d_in, const int* in_sizes, int n_in,
                              void* d_out, int out_size)
{
    const float* w = (const float*)d_in[0];   // edge_weight [K, N*N]
    // d_in[1] = row indices (unused: closed-form e/N), d_in[2] = num_atom
    float* out = (float*)d_out;

    int total = in_sizes[0];                  // K * N * N
    int nrows = total / N_ATOM;               // K * N (32768)
    // 32768 = 3*10922 + 2: last group handles rows beyond nrows? No —
    // 32768 not divisible by 3. Launch ceil groups; guard per-row.
    int ngroups = nrows / ROWS_PER_WARP;      // 10922 full groups
    int rem = nrows - ngroups * ROWS_PER_WARP; // 2 leftover rows

    int threads = 256;
    int warps_per_block = threads / 32;
    int blocks = (ngroups + warps_per_block - 1) / warps_per_block;
    rownorm_3row_kernel<<<blocks, threads>>>(w, out, ngroups);

    if (rem > 0) {
        // Tail rows handled by a tiny second launch reusing the same kernel
        // shape: treat each leftover row as its own "group" of 1 via offset.
        // Simplest: one extra block where each warp does one row.
        // Reuse rownorm_3row? cleaner: small dedicated grid of warp-per-row.
        // Launch 3-row kernel on a region of rem rows is invalid; do scalar.
        // rem <= 2 rows -> 2 warps of work: use one block of 64 threads with
        // the 3-row kernel pointing at the tail with ngroups=rem and
        // ROWS_PER_WARP=1 semantics is not available, so do it inline:
        const float* wt = w + (size_t)ngroups * ROWS_PER_WARP * N_ATOM;
        float* ot = out + (size_t)ngroups * ROWS_PER_WARP * N_ATOM;
        // Tail kernel: warp-per-row (R1 shape), rem rows.
        extern __global__ void rownorm_tail_kernel(const float*, float*, int);
        rownorm_tail_kernel<<<1, 64>>>(wt, ot, rem);
    }
}

// Tail: warp-per-row, identical math to R1.
__global__ __launch_bounds__(64) void rownorm_tail_kernel(
    const float* __restrict__ w,
    float* __restrict__ out,
    int nrows)
{
    int warp = threadIdx.x >> 5;
    int lane = threadIdx.x & 31;
    if (warp >= nrows) return;

    const float4* __restrict__ src =
        reinterpret_cast<const float4*>(w + (size_t)warp * N_ATOM);
    float4* __restrict__ dst =
        reinterpret_cast<float4*>(out + (size_t)warp * N_ATOM);

    float4 v[F4_PER_LANE];
    float s = 0.0f;
#pragma unroll
    for (int i = 0; i < F4_PER_LANE; i++) {
        v[i] = src[lane + i * 32];
        s += (v[i].x + v[i].y) + (v[i].z + v[i].w);
    }
#pragma unroll
    for (int off = 16; off > 0; off >>= 1)
        s += __shfl_xor_sync(0xFFFFFFFFu, s, off);
    float inv = (s > 0.0f) ? (1.0f / s) : 0.0f;
#pragma unroll
    for (int i = 0; i < F4_PER_LANE; i++) {
        float4 t = v[i];
        t.x *= inv; t.y *= inv; t.z *= inv; t.w *= inv;
        dst[lane + i * 32] = t;
    }
}

// round 16
// speedup vs baseline: 1.0310x; 1.0310x over previous
#include <cuda_runtime.h>
#include <cstddef>

// Row-normalize block-diagonal graph — FINAL: two rows per warp, deep
// front-batch (best of 14 rounds of measured variants).
//
// edge_weight: [K, N*N] fp32, N=1024. row[e]=e/N closed-form -> degree of
// source node r = sum of contiguous 1024-float row r. out = w * 1/deg.
// The 128MB `row` index array is never read (index structure is closed-form).
//
// Measured landscape (kernel-time / DRAM%):
//   R1  warp-per-row MLP=8            35.4us / 75.6%
//   R3  reg-capped occupancy push     47.2us / 67.1%   (MLP loss dominates)
//   R6  block-per-row occ=87%         43.8us / 64.0%   (same lesson)
//   R8/R9 L2 evict policies           flat or worse    (no-op at this footprint)
//   R10 THIS: 2 rows/warp MLP=16      34.6us / 77.1%   <- best
//   R12/R13 pipelined variants        36.5-37.5us      (occupancy loss, no overlap win)
//   R14 3 rows/warp + tail launch     worse            (saturated + serial tail)
// Conclusion: ~6.1 TB/s is this chip's mixed read+write ceiling; this kernel
// sits within ~2% of it. Only (resident warps x front-batched loads) mattered;
// scheduling tricks, L2 hints, and occupancy pushes all lost.

static constexpr int N_ATOM = 1024;                    // floats per row
static constexpr int F4_PER_LANE = N_ATOM / (32 * 4);  // 8

__global__ __launch_bounds__(256) void rownorm_2row_kernel(
    const float* __restrict__ w,
    float* __restrict__ out,
    int npairs)   // nrows / 2
{
    int gtid = blockIdx.x * blockDim.x + threadIdx.x;
    int warp = gtid >> 5;
    int lane = threadIdx.x & 31;
    if (warp >= npairs) return;

    const float4* __restrict__ src0 =
        reinterpret_cast<const float4*>(w + (size_t)(2 * warp) * N_ATOM);
    const float4* __restrict__ src1 =
        reinterpret_cast<const float4*>(w + (size_t)(2 * warp + 1) * N_ATOM);
    float4* __restrict__ dst0 =
        reinterpret_cast<float4*>(out + (size_t)(2 * warp) * N_ATOM);
    float4* __restrict__ dst1 =
        reinterpret_cast<float4*>(out + (size_t)(2 * warp + 1) * N_ATOM);

    // Front-batch ALL loads for both rows: 16 outstanding LDG.128/thread.
    float4 v0[F4_PER_LANE], v1[F4_PER_LANE];
    float a = 0.0f, b = 0.0f;
#pragma unroll
    for (int i = 0; i < F4_PER_LANE; i++) {
        v0[i] = src0[lane + i * 32];
        v1[i] = src1[lane + i * 32];
    }
#pragma unroll
    for (int i = 0; i < F4_PER_LANE; i++) {
        a += (v0[i].x + v0[i].y) + (v0[i].z + v0[i].w);
        b += (v1[i].x + v1[i].y) + (v1[i].z + v1[i].w);
    }

    // Two warp tree-reduces (independent chains, interleaved by scheduler).
#pragma unroll
    for (int off = 16; off > 0; off >>= 1) {
        a += __shfl_xor_sync(0xFFFFFFFFu, a, off);
        b += __shfl_xor_sync(0xFFFFFFFFu, b, off);
    }

    float inv0 = (a > 0.0f) ? (1.0f / a) : 0.0f;
    float inv1 = (b > 0.0f) ? (1.0f / b) : 0.0f;

    // Scale in registers, store both rows.
#pragma unroll
    for (int i = 0; i < F4_PER_LANE; i++) {
        float4 t = v0[i];
        t.x *= inv0; t.y *= inv0; t.z *= inv0; t.w *= inv0;
        dst0[lane + i * 32] = t;
        float4 u = v1[i];
        u.x *= inv1; u.y *= inv1; u.z *= inv1; u.w *= inv1;
        dst1[lane + i * 32] = u;
    }
}

extern "C" void kernel_launch(void* const* d_in, const int* in_sizes, int n_in,
                              void* d_out, int out_size)
{
    const float* w = (const float*)d_in[0];   // edge_weight [K, N*N]
    // d_in[1] = row indices (unused: closed-form e/N), d_in[2] = num_atom
    float* out = (float*)d_out;

    int total = in_sizes[0];                  // K * N * N
    int nrows = total / N_ATOM;               // K * N (even: 32768)
    int npairs = nrows / 2;

    int threads = 256;
    int warps_per_block = threads / 32;
    int blocks = (npairs + warps_per_block - 1) / warps_per_block;
    rownorm_2row_kernel<<<blocks, threads>>>(w, out, npairs);
}